// round 12
// baseline (speedup 1.0000x reference)
#include <cuda_runtime.h>
#include <cuda_bf16.h>

#define BS 2048
#define HC 22
#define WX 438
#define C2 20
#define W2O 439
#define KW 12
#define NM 3
#define NE 18
#define NPAIR2 210      /* 20*21/2 */
#define NPAIR1 253      /* 22*23/2 */
#define GSTR (BS*NM*NE*NE)
#define LOGRECT (-9.210340371976184f)

// ---------------- device scratch (no cudaMalloc allowed) ----------------
__device__ float g_S[HC];
__device__ float g_Mu[NPAIR1];
__device__ float g_Wc[HC*KW*C2];     // [h][k][o]
__device__ float g_cpre[C2*13];      // prefix sums of cconst per o
__device__ float g_sum2[C2];
__device__ float g_sumsq2[C2];
__device__ float g_a2[C2];
__device__ float g_covy[(size_t)BS*NM*NPAIR2];   // packed centered grams
__device__ float g_G[(size_t)3*GSTR];            // Q,K,V then logQ,logK,logV in place
__device__ float g_mix[(size_t)BS*NM*NE*NE];     // mixed, then logO in place

__device__ __forceinline__ float warp_sum(float v){
#pragma unroll
    for (int o = 16; o; o >>= 1) v += __shfl_xor_sync(0xffffffffu, v, o);
    return v;
}

// ---------------- K0: zero accumulators ----------------
__global__ void k_init(){
    int t = threadIdx.x;
    if (t < HC)     g_S[t]  = 0.f;
    if (t < NPAIR1) g_Mu[t] = 0.f;
    if (t < C2){ g_sum2[t] = 0.f; g_sumsq2[t] = 0.f; }
}

// ---------------- K1: per-channel sum + Gram of x (float2 dots) ----------------
__global__ void k_stats1(const float* __restrict__ x){
    __shared__ float xs[HC*440];   // even pitch -> float2 aligned
    int tid = threadIdx.x, b = blockIdx.x;
    const float* xb = x + (size_t)b*HC*WX;
    for (int h = 0; h < HC; h++)
        for (int w = tid; w < WX; w += 256) xs[h*440 + w] = xb[h*WX + w];
    __syncthreads();
    for (int task = tid; task < NPAIR1 + HC; task += 256){
        if (task < NPAIR1){
            int c = 0, rem = task;
            while (rem >= HC - c){ rem -= HC - c; c++; }
            int d = c + rem;
            const float2* rc = (const float2*)(xs + c*440);
            const float2* rd = (const float2*)(xs + d*440);
            float s0 = 0.f, s1 = 0.f;
            for (int w = 0; w < WX/2; w++){
                float2 a = rc[w], e = rd[w];
                s0 += a.x*e.x; s1 += a.y*e.y;
            }
            atomicAdd(&g_Mu[task], s0 + s1);
        } else {
            int h = task - NPAIR1;
            const float2* rh = (const float2*)(xs + h*440);
            float s0 = 0.f, s1 = 0.f;
            for (int w = 0; w < WX/2; w++){ float2 a = rh[w]; s0 += a.x; s1 += a.y; }
            atomicAdd(&g_S[h], s0 + s1);
        }
    }
}

// ---------------- K2: fold conv1+BN1 into composite conv2 weights ----------------
__global__ void k_prep(const float* __restrict__ W1, const float* __restrict__ b1,
                       const float* __restrict__ g1, const float* __restrict__ be1,
                       const float* __restrict__ W2){
    __shared__ float mx[HC], Cx[HC*HC], W1s[HC*HC], a1[HC], hc[HC], ccs[KW*C2];
    int tid = threadIdx.x;
    const float invN = 1.f/((float)BS*(float)WX);
    if (tid < HC) mx[tid] = g_S[tid]*invN;
    for (int t = tid; t < HC*HC; t += blockDim.x) W1s[t] = W1[t];  // [o][h]
    __syncthreads();
    for (int t = tid; t < NPAIR1; t += blockDim.x){
        int c = 0, rem = t;
        while (rem >= HC - c){ rem -= HC - c; c++; }
        int d = c + rem;
        float v = g_Mu[t]*invN - mx[c]*mx[d];
        Cx[c*HC+d] = v; Cx[d*HC+c] = v;
    }
    __syncthreads();
    if (tid < HC){
        int o = tid;
        float m1 = b1[o];
        for (int h = 0; h < HC; h++) m1 += W1s[o*HC+h]*mx[h];
        float var = 0.f;
        for (int h = 0; h < HC; h++){
            float wh = W1s[o*HC+h];
            float s = 0.f;
            for (int h2 = 0; h2 < HC; h2++) s += W1s[o*HC+h2]*Cx[h*HC+h2];
            var += wh*s;
        }
        float a = g1[o]*rsqrtf(var + 1e-5f);
        a1[o] = a;
        hc[o] = a*(b1[o]-m1) + be1[o];     // constant part of h1
    }
    __syncthreads();
    for (int t = tid; t < KW*C2; t += blockDim.x){
        int k = t/C2, o = t%C2;
        float s = 0.f;
        for (int c = 0; c < HC; c++) s += W2[(o*HC+c)*KW+k]*hc[c];
        ccs[k*C2+o] = s;
    }
    for (int t = tid; t < HC*KW*C2; t += blockDim.x){
        int o = t%C2; int hk = t/C2; int k = hk%KW; int h = hk/KW;
        float s = 0.f;
        for (int c = 0; c < HC; c++) s += W2[(o*HC+c)*KW+k]*a1[c]*W1s[c*HC+h];
        g_Wc[t] = s;
    }
    __syncthreads();
    if (tid < C2){
        int o = tid; float run = 0.f;
        g_cpre[o*13+0] = 0.f;
        for (int k = 0; k < KW; k++){ run += ccs[k*C2+o]; g_cpre[o*13+k+1] = run; }
    }
}

// ---------------- K3: conv2 (on x) + patch covariances + BN2 sums ----------------
// Weights read via __ldg (L1) instead of SMEM -> 76.8KB SMEM -> 3 blocks/SM.
// Block 352: 680 tasks -> max 2 per thread (was 3 at 256).
#define PX 454
#define PY 444
#define CHW 13
#define NCHK 34
#define CBLK 352
#define CONV_SMEM_FLOATS (HC*PX + C2*PY + C2*13 + NM*C2)

__global__ void __launch_bounds__(CBLK) k_conv(const float* __restrict__ x){
    extern __shared__ float sm[];
    float* xs  = sm;                   // HC*PX, zero-padded 6 both sides
    float* ys  = xs + HC*PX;           // C2*PY
    float* cps = ys + C2*PY;           // C2*13
    float* Sp  = cps + C2*13;          // NM*C2
    int tid = threadIdx.x, b = blockIdx.x;
    const float* xb = x + (size_t)b*HC*WX;
    for (int h = 0; h < HC; h++)
        for (int c = tid; c < PX; c += CBLK)
            xs[h*PX + c] = (c >= 6 && c < 6+WX) ? xb[h*WX + (c-6)] : 0.f;
    if (tid < C2*13) cps[tid] = g_cpre[tid];
    __syncthreads();

    const float* wcg = (const float*)g_Wc;
    for (int task = tid; task < C2*NCHK; task += CBLK){
        int o = task / NCHK, ch = task % NCHK;
        int wbase = ch*CHW;
        float acc[CHW];
#pragma unroll
        for (int j = 0; j < CHW; j++) acc[j] = 0.f;
        for (int h = 0; h < HC; h++){
            const float* xr0 = xs + h*PX + wbase;
            float xr[CHW+KW-1];
#pragma unroll
            for (int c = 0; c < CHW+KW-1; c++) xr[c] = xr0[c];
            const float* wrow = wcg + h*KW*C2 + o;
#pragma unroll
            for (int k = 0; k < KW; k++){
                float wv = __ldg(wrow + k*C2);
#pragma unroll
                for (int j = 0; j < CHW; j++) acc[j] += wv*xr[j+k];
            }
        }
#pragma unroll
        for (int j = 0; j < CHW; j++){
            int w = wbase + j;
            if (w < W2O){
                int kmin = 6 - w;   if (kmin < 0)  kmin = 0;
                int kmax = 444 - w; if (kmax > KW) kmax = KW;
                acc[j] += cps[o*13+kmax] - cps[o*13+kmin];
                ys[o*PY + w] = acc[j];
            }
        }
    }
    __syncthreads();

    // per-patch channel sums
    if (tid < NM*C2){
        int m = tid/C2, c = tid%C2;
        int lo = (m==0)?0:(m==1?147:293);
        int hi = (m==0)?147:(m==1?293:439);
        float s = 0.f;
        const float* yc = ys + c*PY;
        for (int w = lo; w < hi; w++) s += yc[w];
        Sp[m*C2+c] = s;
    }
    __syncthreads();

    // per-patch centered grams + BN2 sums
    if (tid < NPAIR2){
        int c = 0, rem = tid;
        while (rem >= C2 - c){ rem -= C2 - c; c++; }
        int d = c + rem;
        const float* yc = ys + c*PY;
        const float* yd = ys + d*PY;
        float sq = 0.f;
        for (int m = 0; m < NM; m++){
            int lo = (m==0)?0:(m==1?147:293);
            int hi = (m==0)?147:(m==1?293:439);
            float pp = 0.f;
            for (int w = lo; w < hi; w++) pp += yc[w]*yd[w];
            float L = (float)(hi - lo);
            float cc = pp - Sp[m*C2+c]*Sp[m*C2+d]/L;
            g_covy[((size_t)(b*NM+m))*NPAIR2 + tid] = cc;
            if (c == d) sq += pp;
        }
        if (c == d){
            atomicAdd(&g_sumsq2[c], sq);
            atomicAdd(&g_sum2[c], Sp[0*C2+c] + Sp[1*C2+c] + Sp[2*C2+c]);
        }
    }
}

// ---------------- K4: BN2 scale ----------------
__global__ void k_bn2(const float* __restrict__ g2){
    int o = threadIdx.x;
    if (o < C2){
        const float invN = 1.f/((float)BS*(float)W2O);
        float mean = g_sum2[o]*invN;
        float var  = g_sumsq2[o]*invN - mean*mean;
        g_a2[o] = g2[o]*rsqrtf(var + 1e-5f);
    }
}

// ---------------- K5: build Q,K,V = W^T X W ----------------
__global__ void k_qkv(const float* __restrict__ Wq, const float* __restrict__ Wk,
                      const float* __restrict__ Wv){
    __shared__ float a2s[C2], Xs[C2*21], Ws[3*C2*NE], Ts[C2*NE];
    __shared__ float invt;
    int tid = threadIdx.x; int bm = blockIdx.x;
    if (tid < C2) a2s[tid] = g_a2[tid];
    for (int t = tid; t < C2*NE; t += 128){
        Ws[t] = Wq[t]; Ws[C2*NE+t] = Wk[t]; Ws[2*C2*NE+t] = Wv[t];
    }
    __syncthreads();
    for (int t = tid; t < NPAIR2; t += 128){
        int c = 0, rem = t;
        while (rem >= C2 - c){ rem -= C2 - c; c++; }
        int d = c + rem;
        float v = a2s[c]*a2s[d]*g_covy[(size_t)bm*NPAIR2 + t];
        Xs[c*21+d] = v; Xs[d*21+c] = v;
    }
    __syncthreads();
    if (tid == 0){
        float tr = 0.f;
        for (int c = 0; c < C2; c++) tr += Xs[c*21+c];
        invt = 1.f/tr;
    }
    __syncthreads();
    for (int pl = 0; pl < 3; pl++){
        const float* W = Ws + pl*C2*NE;
        for (int t = tid; t < C2*NE; t += 128){
            int i = t/NE, j = t%NE;
            float s = 0.f;
            for (int p = 0; p < C2; p++) s += Xs[i*21+p]*W[p*NE+j];
            Ts[t] = s*invt + 1e-5f*W[i*NE+j];      // (X/tr + 1e-5 I) W
        }
        __syncthreads();
        float* dst = g_G + (size_t)pl*GSTR + (size_t)bm*NE*NE;
        for (int t = tid; t < NE*NE; t += 128){
            int i = t/NE, j = t%NE;
            float s = 0.f;
            for (int p = 0; p < C2; p++) s += W[p*NE+i]*Ts[p*NE+j];
            dst[t] = s;
        }
        __syncthreads();
    }
}

// ---------------- K6: tournament Jacobi eigh, hoisted schedule + packed params ----------------
#define EPIT 19
#define VOFF (NE*EPIT)
#define EW 8
__global__ void __launch_bounds__(EW*32) k_eig(int which, int nmat, int mode){
    __shared__ float  sAV[EW][2*VOFF];
    __shared__ float2 sCS[EW][9];
    __shared__ int2   sRO[EW][9];   // (p*EPIT, q*EPIT)
    __shared__ int2   sPQ[EW][9];   // (p, q)
    int lane = threadIdx.x & 31, wid = threadIdx.x >> 5;
    int mat = blockIdx.x*EW + wid;
    if (mat >= nmat) return;
    float* A = sAV[wid];
    float* V = A + VOFF;
    float* src = (which ? g_mix : g_G) + (size_t)mat*NE*NE;

    // per-lane loop-invariant item schedule: 162 items = (pair k, element e)
    int itk[6], ite[6], iteb[6]; bool itv[6];
#pragma unroll
    for (int u = 0; u < 6; u++){
        int it = lane + 32*u;
        itv[u] = (it < 162);
        int itc = itv[u] ? it : 0;
        itk[u] = itc/18; ite[u] = itc - itk[u]*18; iteb[u] = ite[u]*EPIT;
    }

    float na = 0.f;
    for (int idx = lane; idx < NE*NE; idx += 32){
        int i = idx/NE, j = idx - i*NE;
        float v = 0.5f*(src[idx] + src[j*NE+i]);  // symmetrize
        A[i*EPIT+j] = v;
        V[i*EPIT+j] = (i == j) ? 1.f : 0.f;
        na += v*v;
    }
    na = warp_sum(na);
    float thr = 1e-13f*na + 1e-37f;
    __syncwarp();

    for (int sweep = 0; sweep < 16; sweep++){
        float off = 0.f;
        for (int idx = lane; idx < NE*NE; idx += 32){
            int i = idx/NE, j = idx - i*NE;
            if (i != j){ float v = A[i*EPIT+j]; off += v*v; }
        }
        off = warp_sum(off);
        if (off <= thr) break;

        for (int r = 0; r < 17; r++){
            if (lane < 9){
                int a, b;
                if (lane == 0){ a = 0; b = 1 + (16 + r) % 17; }
                else { a = 1 + (lane - 1 + r) % 17; b = 1 + (16 - lane + r) % 17; }
                int p = min(a, b), q = max(a, b);
                float apq = A[p*EPIT+q];
                float c = 1.f, s = 0.f;
                if (apq != 0.f){
                    float app = A[p*EPIT+p], aqq = A[q*EPIT+q];
                    float tau = (aqq - app)/(2.f*apq);
                    float t = ((tau >= 0.f) ? 1.f : -1.f)/(fabsf(tau) + sqrtf(1.f + tau*tau));
                    c = rsqrtf(1.f + t*t);
                    s = t*c;
                }
                sCS[wid][lane] = make_float2(c, s);
                sRO[wid][lane] = make_int2(p*EPIT, q*EPIT);
                sPQ[wid][lane] = make_int2(p, q);
            }
            __syncwarp();
            // row updates
#pragma unroll
            for (int u = 0; u < 6; u++) if (itv[u]){
                float2 cs = sCS[wid][itk[u]];
                int2  ro = sRO[wid][itk[u]];
                int j = ite[u];
                float a0 = A[ro.x+j], a1 = A[ro.y+j];
                A[ro.x+j] = cs.x*a0 - cs.y*a1;
                A[ro.y+j] = cs.y*a0 + cs.x*a1;
            }
            __syncwarp();
            // column + eigenvector updates
#pragma unroll
            for (int u = 0; u < 6; u++) if (itv[u]){
                float2 cs = sCS[wid][itk[u]];
                int2  pq = sPQ[wid][itk[u]];
                int ib = iteb[u];
                float ap = A[ib+pq.x], aq = A[ib+pq.y];
                A[ib+pq.x] = cs.x*ap - cs.y*aq;
                A[ib+pq.y] = cs.y*ap + cs.x*aq;
                float vp = V[ib+pq.x], vq = V[ib+pq.y];
                V[ib+pq.x] = cs.x*vp - cs.y*vq;
                V[ib+pq.y] = cs.y*vp + cs.x*vq;
            }
            __syncwarp();
        }
    }
    __syncwarp();
    if (lane < NE){
        float wj[NE];
#pragma unroll
        for (int k = 0; k < NE; k++){
            float lam = A[k*EPIT+k];
            float f = mode ? fmaxf(lam, LOGRECT) : logf(fmaxf(lam, 1e-30f));
            wj[k] = f * V[lane*EPIT+k];
        }
        for (int i = 0; i < NE; i++){
            float s = 0.f;
#pragma unroll
            for (int k = 0; k < NE; k++) s += V[i*EPIT+k]*wj[k];
            src[i*NE+lane] = s;
        }
    }
}

// ---------------- K7: energy / softmax / mix ----------------
__global__ void k_attn(){
    __shared__ float Qs[NM*324], Ks[NM*324], Vs[NM*324], sE[9], sP[9];
    int tid = threadIdx.x, b = blockIdx.x;
    for (int t = tid; t < NM*324; t += 128){
        size_t off = (size_t)b*NM*324 + t;
        Qs[t] = g_G[off];
        Ks[t] = g_G[(size_t)GSTR + off];
        Vs[t] = g_G[(size_t)2*GSTR + off];
    }
    if (tid < 9) sE[tid] = 0.f;
    __syncthreads();
    float e[9];
#pragma unroll
    for (int i = 0; i < 9; i++) e[i] = 0.f;
    for (int idx = tid; idx < 324; idx += 128){
        float q0 = Qs[idx], q1 = Qs[324+idx], q2 = Qs[648+idx];
        float k0 = Ks[idx], k1 = Ks[324+idx], k2 = Ks[648+idx];
        float d;
        d = q0-k0; e[0] += d*d;  d = q0-k1; e[1] += d*d;  d = q0-k2; e[2] += d*d;
        d = q1-k0; e[3] += d*d;  d = q1-k1; e[4] += d*d;  d = q1-k2; e[5] += d*d;
        d = q2-k0; e[6] += d*d;  d = q2-k1; e[7] += d*d;  d = q2-k2; e[8] += d*d;
    }
#pragma unroll
    for (int i = 0; i < 9; i++){
        float v = warp_sum(e[i]);
        if ((tid & 31) == 0) atomicAdd(&sE[i], v);
    }
    __syncthreads();
    if (tid == 0){
        for (int j = 0; j < 3; j++){
            float s0 = 1.f/(1.f + log1pf(sE[j*3+0]));
            float s1 = 1.f/(1.f + log1pf(sE[j*3+1]));
            float s2 = 1.f/(1.f + log1pf(sE[j*3+2]));
            float mx = fmaxf(s0, fmaxf(s1, s2));
            float e0 = expf(s0-mx), e1 = expf(s1-mx), e2 = expf(s2-mx);
            float inv = 1.f/(e0+e1+e2);
            sP[j*3+0] = e0*inv; sP[j*3+1] = e1*inv; sP[j*3+2] = e2*inv;
        }
    }
    __syncthreads();
    for (int idx = tid; idx < NM*324; idx += 128){
        int j = idx/324, ee = idx%324;
        float v = sP[j*3+0]*Vs[ee] + sP[j*3+1]*Vs[324+ee] + sP[j*3+2]*Vs[648+ee];
        g_mix[((size_t)b*NM + j)*324 + ee] = v;
    }
}

// ---------------- K8: triu-vec @ Wl + bl ----------------
__global__ void k_final(const float* __restrict__ Wl, const float* __restrict__ bl,
                        float* __restrict__ out){
    __shared__ float red[4];
    int tid = threadIdx.x, b = blockIdx.x;
    if (tid < 4) red[tid] = 0.f;
    __syncthreads();
    float a0 = 0.f, a1 = 0.f, a2 = 0.f, a3 = 0.f;
    for (int idx = tid; idx < 513; idx += 128){
        int m = idx/171, t = idx%171;
        int r = 0, rem = t;
        while (rem >= NE - r){ rem -= NE - r; r++; }
        int c = r + rem;
        float v = g_mix[((size_t)b*NM + m)*324 + r*NE + c];
        const float* wl = Wl + (size_t)idx*4;
        a0 += v*wl[0]; a1 += v*wl[1]; a2 += v*wl[2]; a3 += v*wl[3];
    }
    a0 = warp_sum(a0); a1 = warp_sum(a1); a2 = warp_sum(a2); a3 = warp_sum(a3);
    if ((tid & 31) == 0){
        atomicAdd(&red[0], a0); atomicAdd(&red[1], a1);
        atomicAdd(&red[2], a2); atomicAdd(&red[3], a3);
    }
    __syncthreads();
    if (tid < 4) out[b*4 + tid] = red[tid] + bl[tid];
}

// ---------------- host launcher ----------------
extern "C" void kernel_launch(void* const* d_in, const int* in_sizes, int n_in,
                              void* d_out, int out_size){
    const float* x   = (const float*)d_in[0];
    const float* W1  = (const float*)d_in[1];
    const float* b1  = (const float*)d_in[2];
    const float* g1  = (const float*)d_in[3];
    const float* be1 = (const float*)d_in[4];
    const float* W2  = (const float*)d_in[5];
    /* b2 = d_in[6] cancels */
    const float* g2  = (const float*)d_in[7];
    /* be2 = d_in[8] cancels */
    const float* Wq  = (const float*)d_in[9];
    const float* Wk  = (const float*)d_in[10];
    const float* Wv  = (const float*)d_in[11];
    const float* Wl  = (const float*)d_in[12];
    const float* bl  = (const float*)d_in[13];
    float* out = (float*)d_out;

    size_t conv_smem = (size_t)CONV_SMEM_FLOATS * sizeof(float);  // 76,752 B -> 3 blocks/SM
    cudaFuncSetAttribute(k_conv, cudaFuncAttributeMaxDynamicSharedMemorySize, (int)conv_smem);

    k_init  <<<1, 256>>>();
    k_stats1<<<BS, 256>>>(x);
    k_prep  <<<1, 256>>>(W1, b1, g1, be1, W2);
    k_conv  <<<BS, CBLK, conv_smem>>>(x);
    k_bn2   <<<1, 32>>>(g2);
    k_qkv   <<<BS*NM, 128>>>(Wq, Wk, Wv);
    k_eig   <<<(3*BS*NM + EW-1)/EW, EW*32>>>(0, 3*BS*NM, 0);   // logQ/logK/logV
    k_attn  <<<BS, 128>>>();
    k_eig   <<<(BS*NM + EW-1)/EW, EW*32>>>(1, BS*NM, 1);       // logO (exp->rect->log collapsed)
    k_final <<<BS, 128>>>(Wl, bl, out);
}

// round 14
// speedup vs baseline: 1.6806x; 1.6806x over previous
#include <cuda_runtime.h>
#include <cuda_bf16.h>

#define BS 2048
#define HC 22
#define WX 438
#define C2 20
#define W2O 439
#define KW 12
#define NM 3
#define NE 18
#define NPAIR2 210      /* 20*21/2 */
#define NPAIR1 253      /* 22*23/2 */
#define GSTR (BS*NM*NE*NE)
#define LOGRECT (-9.210340371976184f)

// ---------------- device scratch (no cudaMalloc allowed) ----------------
__device__ float g_S[HC];
__device__ float g_Mu[NPAIR1];
__device__ float g_Wc[HC*KW*C2];     // [h][k][o]
__device__ float g_cpre[C2*13];      // prefix sums of cconst per o
__device__ float g_sum2[C2];
__device__ float g_sumsq2[C2];
__device__ float g_a2[C2];
__device__ float g_covy[(size_t)BS*NM*NPAIR2];   // packed centered grams
__device__ float g_G[(size_t)3*GSTR];            // Q,K,V then logQ,logK,logV in place
__device__ float g_mix[(size_t)BS*NM*NE*NE];     // mixed, then logO in place

__device__ __forceinline__ float warp_sum(float v){
#pragma unroll
    for (int o = 16; o; o >>= 1) v += __shfl_xor_sync(0xffffffffu, v, o);
    return v;
}

// ---------------- K0: zero accumulators ----------------
__global__ void k_init(){
    int t = threadIdx.x;
    if (t < HC)     g_S[t]  = 0.f;
    if (t < NPAIR1) g_Mu[t] = 0.f;
    if (t < C2){ g_sum2[t] = 0.f; g_sumsq2[t] = 0.f; }
}

// ---------------- K1: per-channel sum + Gram of x ----------------
__global__ void k_stats1(const float* __restrict__ x){
    __shared__ float xs[HC*439];   // pitch 439 (odd -> conflict free col access)
    int tid = threadIdx.x, b = blockIdx.x;
    const float* xb = x + (size_t)b*HC*WX;
    for (int idx = tid; idx < HC*WX; idx += 256)
        xs[(idx/WX)*439 + idx%WX] = xb[idx];
    __syncthreads();
    for (int task = tid; task < NPAIR1 + HC; task += 256){
        if (task < NPAIR1){
            int c = 0, rem = task;
            while (rem >= HC - c){ rem -= HC - c; c++; }
            int d = c + rem;
            const float* rc = xs + c*439;
            const float* rd = xs + d*439;
            float s = 0.f;
            for (int w = 0; w < WX; w++) s += rc[w]*rd[w];
            atomicAdd(&g_Mu[task], s);
        } else {
            int h = task - NPAIR1;
            const float* rh = xs + h*439;
            float s = 0.f;
            for (int w = 0; w < WX; w++) s += rh[w];
            atomicAdd(&g_S[h], s);
        }
    }
}

// ---------------- K2: fold conv1+BN1 into composite conv2 weights ----------------
__global__ void k_prep(const float* __restrict__ W1, const float* __restrict__ b1,
                       const float* __restrict__ g1, const float* __restrict__ be1,
                       const float* __restrict__ W2){
    __shared__ float mx[HC], Cx[HC*HC], W1s[HC*HC], a1[HC], hc[HC], ccs[KW*C2];
    int tid = threadIdx.x;
    const float invN = 1.f/((float)BS*(float)WX);
    if (tid < HC) mx[tid] = g_S[tid]*invN;
    for (int t = tid; t < HC*HC; t += blockDim.x) W1s[t] = W1[t];  // [o][h]
    __syncthreads();
    for (int t = tid; t < NPAIR1; t += blockDim.x){
        int c = 0, rem = t;
        while (rem >= HC - c){ rem -= HC - c; c++; }
        int d = c + rem;
        float v = g_Mu[t]*invN - mx[c]*mx[d];
        Cx[c*HC+d] = v; Cx[d*HC+c] = v;
    }
    __syncthreads();
    if (tid < HC){
        int o = tid;
        float m1 = b1[o];
        for (int h = 0; h < HC; h++) m1 += W1s[o*HC+h]*mx[h];
        float var = 0.f;
        for (int h = 0; h < HC; h++){
            float wh = W1s[o*HC+h];
            float s = 0.f;
            for (int h2 = 0; h2 < HC; h2++) s += W1s[o*HC+h2]*Cx[h*HC+h2];
            var += wh*s;
        }
        float a = g1[o]*rsqrtf(var + 1e-5f);
        a1[o] = a;
        hc[o] = a*(b1[o]-m1) + be1[o];     // constant part of h1
    }
    __syncthreads();
    for (int t = tid; t < KW*C2; t += blockDim.x){
        int k = t/C2, o = t%C2;
        float s = 0.f;
        for (int c = 0; c < HC; c++) s += W2[(o*HC+c)*KW+k]*hc[c];
        ccs[k*C2+o] = s;
    }
    for (int t = tid; t < HC*KW*C2; t += blockDim.x){
        int o = t%C2; int hk = t/C2; int k = hk%KW; int h = hk/KW;
        float s = 0.f;
        for (int c = 0; c < HC; c++) s += W2[(o*HC+c)*KW+k]*a1[c]*W1s[c*HC+h];
        g_Wc[t] = s;
    }
    __syncthreads();
    if (tid < C2){
        int o = tid; float run = 0.f;
        g_cpre[o*13+0] = 0.f;
        for (int k = 0; k < KW; k++){ run += ccs[k*C2+o]; g_cpre[o*13+k+1] = run; }
    }
}

// ---------------- K3: conv2 (on x) + patch covariances + BN2 sums ----------------
// R11 structure (SMEM weights) with block=340: 680 tasks -> exactly 2/thread.
#define PX 454
#define PY 443
#define CHW 13
#define NCHK 34
#define CBLK 340
#define CONV_SMEM_FLOATS (HC*PX + C2*PY + HC*KW*C2 + C2*13 + NM*C2)

__global__ void __launch_bounds__(CBLK) k_conv(const float* __restrict__ x){
    extern __shared__ float sm[];
    float* xs  = sm;                   // HC*PX, zero-padded 6 both sides
    float* ys  = xs + HC*PX;           // C2*PY
    float* wcs = ys + C2*PY;           // HC*KW*C2
    float* cps = wcs + HC*KW*C2;       // C2*13
    float* Sp  = cps + C2*13;          // NM*C2
    int tid = threadIdx.x, b = blockIdx.x;
    const float* xb = x + (size_t)b*HC*WX;
    for (int idx = tid; idx < HC*PX; idx += CBLK){
        int h = idx/PX, c = idx%PX;
        xs[idx] = (c >= 6 && c < 6+WX) ? xb[h*WX + (c-6)] : 0.f;
    }
    for (int idx = tid; idx < HC*KW*C2; idx += CBLK) wcs[idx] = g_Wc[idx];
    for (int idx = tid; idx < C2*13; idx += CBLK)    cps[idx] = g_cpre[idx];
    __syncthreads();

    for (int task = tid; task < C2*NCHK; task += CBLK){
        int o = task / NCHK, ch = task % NCHK;
        int wbase = ch*CHW;
        float acc[CHW];
#pragma unroll
        for (int j = 0; j < CHW; j++) acc[j] = 0.f;
        for (int h = 0; h < HC; h++){
            const float* xr0 = xs + h*PX + wbase;
            float xr[CHW+KW-1];
#pragma unroll
            for (int c = 0; c < CHW+KW-1; c++) xr[c] = xr0[c];
            const float* wrow = wcs + h*KW*C2 + o;
#pragma unroll
            for (int k = 0; k < KW; k++){
                float wv = wrow[k*C2];
#pragma unroll
                for (int j = 0; j < CHW; j++) acc[j] += wv*xr[j+k];
            }
        }
#pragma unroll
        for (int j = 0; j < CHW; j++){
            int w = wbase + j;
            if (w < W2O){
                int kmin = 6 - w;   if (kmin < 0)  kmin = 0;
                int kmax = 444 - w; if (kmax > KW) kmax = KW;
                acc[j] += cps[o*13+kmax] - cps[o*13+kmin];
                ys[o*PY + w] = acc[j];
            }
        }
    }
    __syncthreads();

    // per-patch channel sums
    if (tid < NM*C2){
        int m = tid/C2, c = tid%C2;
        int lo = (m==0)?0:(m==1?147:293);
        int hi = (m==0)?147:(m==1?293:439);
        float s = 0.f;
        const float* yc = ys + c*PY;
        for (int w = lo; w < hi; w++) s += yc[w];
        Sp[m*C2+c] = s;
    }
    __syncthreads();

    // per-patch centered grams + BN2 sums
    if (tid < NPAIR2){
        int c = 0, rem = tid;
        while (rem >= C2 - c){ rem -= C2 - c; c++; }
        int d = c + rem;
        const float* yc = ys + c*PY;
        const float* yd = ys + d*PY;
        float sq = 0.f;
        for (int m = 0; m < NM; m++){
            int lo = (m==0)?0:(m==1?147:293);
            int hi = (m==0)?147:(m==1?293:439);
            float pp = 0.f;
            for (int w = lo; w < hi; w++) pp += yc[w]*yd[w];
            float L = (float)(hi - lo);
            float cc = pp - Sp[m*C2+c]*Sp[m*C2+d]/L;
            g_covy[((size_t)(b*NM+m))*NPAIR2 + tid] = cc;
            if (c == d) sq += pp;
        }
        if (c == d){
            atomicAdd(&g_sumsq2[c], sq);
            atomicAdd(&g_sum2[c], Sp[0*C2+c] + Sp[1*C2+c] + Sp[2*C2+c]);
        }
    }
}

// ---------------- K4: BN2 scale ----------------
__global__ void k_bn2(const float* __restrict__ g2){
    int o = threadIdx.x;
    if (o < C2){
        const float invN = 1.f/((float)BS*(float)W2O);
        float mean = g_sum2[o]*invN;
        float var  = g_sumsq2[o]*invN - mean*mean;
        g_a2[o] = g2[o]*rsqrtf(var + 1e-5f);
    }
}

// ---------------- K5: build Q,K,V = W^T X W ----------------
__global__ void k_qkv(const float* __restrict__ Wq, const float* __restrict__ Wk,
                      const float* __restrict__ Wv){
    __shared__ float a2s[C2], Xs[C2*21], Ws[3*C2*NE], Ts[C2*NE];
    __shared__ float invt;
    int tid = threadIdx.x; int bm = blockIdx.x;
    if (tid < C2) a2s[tid] = g_a2[tid];
    for (int t = tid; t < C2*NE; t += 128){
        Ws[t] = Wq[t]; Ws[C2*NE+t] = Wk[t]; Ws[2*C2*NE+t] = Wv[t];
    }
    __syncthreads();
    for (int t = tid; t < NPAIR2; t += 128){
        int c = 0, rem = t;
        while (rem >= C2 - c){ rem -= C2 - c; c++; }
        int d = c + rem;
        float v = a2s[c]*a2s[d]*g_covy[(size_t)bm*NPAIR2 + t];
        Xs[c*21+d] = v; Xs[d*21+c] = v;
    }
    __syncthreads();
    if (tid == 0){
        float tr = 0.f;
        for (int c = 0; c < C2; c++) tr += Xs[c*21+c];
        invt = 1.f/tr;
    }
    __syncthreads();
    for (int pl = 0; pl < 3; pl++){
        const float* W = Ws + pl*C2*NE;
        for (int t = tid; t < C2*NE; t += 128){
            int i = t/NE, j = t%NE;
            float s = 0.f;
            for (int p = 0; p < C2; p++) s += Xs[i*21+p]*W[p*NE+j];
            Ts[t] = s*invt + 1e-5f*W[i*NE+j];      // (X/tr + 1e-5 I) W
        }
        __syncthreads();
        float* dst = g_G + (size_t)pl*GSTR + (size_t)bm*NE*NE;
        for (int t = tid; t < NE*NE; t += 128){
            int i = t/NE, j = t%NE;
            float s = 0.f;
            for (int p = 0; p < C2; p++) s += W[p*NE+i]*Ts[p*NE+j];
            dst[t] = s;
        }
        __syncthreads();
    }
}

// ---------------- K6: tournament Jacobi eigh (R11 structure, float4-packed params) ----------------
#define EPIT 19
#define EW 8
__global__ void __launch_bounds__(EW*32) k_eig(int which, int nmat, int mode){
    __shared__ float  sA[EW][NE*EPIT];
    __shared__ float  sV[EW][NE*EPIT];
    __shared__ float4 sP4[EW][9];   // (c, s, p-as-float-bits, q-as-float-bits)
    int lane = threadIdx.x & 31, wid = threadIdx.x >> 5;
    int mat = blockIdx.x*EW + wid;
    if (mat >= nmat) return;
    float* A = sA[wid];
    float* V = sV[wid];
    float* src = (which ? g_mix : g_G) + (size_t)mat*NE*NE;

    float na = 0.f;
    for (int idx = lane; idx < NE*NE; idx += 32){
        int i = idx/NE, j = idx - i*NE;
        float v = 0.5f*(src[idx] + src[j*NE+i]);  // symmetrize
        A[i*EPIT+j] = v;
        V[i*EPIT+j] = (i == j) ? 1.f : 0.f;
        na += v*v;
    }
    na = warp_sum(na);
    float thr = 1e-13f*na + 1e-37f;
    __syncwarp();

    for (int sweep = 0; sweep < 16; sweep++){
        float off = 0.f;
        for (int idx = lane; idx < NE*NE; idx += 32){
            int i = idx/NE, j = idx - i*NE;
            if (i != j){ float v = A[i*EPIT+j]; off += v*v; }
        }
        off = warp_sum(off);
        if (off <= thr) break;

        for (int r = 0; r < 17; r++){
            if (lane < 9){
                int a, b;
                if (lane == 0){ a = 0; b = 1 + (16 + r) % 17; }
                else { a = 1 + (lane - 1 + r) % 17; b = 1 + (16 - lane + r) % 17; }
                int p = min(a, b), q = max(a, b);
                float apq = A[p*EPIT+q];
                float c = 1.f, s = 0.f;
                if (apq != 0.f){
                    float app = A[p*EPIT+p], aqq = A[q*EPIT+q];
                    float tau = (aqq - app)/(2.f*apq);
                    float t = ((tau >= 0.f) ? 1.f : -1.f)/(fabsf(tau) + sqrtf(1.f + tau*tau));
                    c = rsqrtf(1.f + t*t);
                    s = t*c;
                }
                sP4[wid][lane] = make_float4(c, s, __int_as_float(p), __int_as_float(q));
            }
            __syncwarp();
            // row updates: all items independent (disjoint pairs, unique (row,col))
            for (int it = lane; it < 162; it += 32){
                int k = it/18, j = it - k*18;
                float4 pk = sP4[wid][k];
                int p = __float_as_int(pk.z), q = __float_as_int(pk.w);
                float apj = A[p*EPIT+j], aqj = A[q*EPIT+j];
                A[p*EPIT+j] = pk.x*apj - pk.y*aqj;
                A[q*EPIT+j] = pk.y*apj + pk.x*aqj;
            }
            __syncwarp();
            // column + eigenvector updates
            for (int it = lane; it < 162; it += 32){
                int k = it/18, i = it - k*18;
                float4 pk = sP4[wid][k];
                int p = __float_as_int(pk.z), q = __float_as_int(pk.w);
                int ib = i*EPIT;
                float aip = A[ib+p], aiq = A[ib+q];
                A[ib+p] = pk.x*aip - pk.y*aiq;
                A[ib+q] = pk.y*aip + pk.x*aiq;
                float vip = V[ib+p], viq = V[ib+q];
                V[ib+p] = pk.x*vip - pk.y*viq;
                V[ib+q] = pk.y*vip + pk.x*viq;
            }
            __syncwarp();
        }
    }
    __syncwarp();
    if (lane < NE){
        float wj[NE];
#pragma unroll
        for (int k = 0; k < NE; k++){
            float lam = A[k*EPIT+k];
            float f = mode ? fmaxf(lam, LOGRECT) : logf(fmaxf(lam, 1e-30f));
            wj[k] = f * V[lane*EPIT+k];
        }
        for (int i = 0; i < NE; i++){
            float s = 0.f;
#pragma unroll
            for (int k = 0; k < NE; k++) s += V[i*EPIT+k]*wj[k];
            src[i*NE+lane] = s;
        }
    }
}

// ---------------- K7: energy / softmax / mix ----------------
__global__ void k_attn(){
    __shared__ float Qs[NM*324], Ks[NM*324], Vs[NM*324], sE[9], sP[9];
    int tid = threadIdx.x, b = blockIdx.x;
    for (int t = tid; t < NM*324; t += 128){
        size_t off = (size_t)b*NM*324 + t;
        Qs[t] = g_G[off];
        Ks[t] = g_G[(size_t)GSTR + off];
        Vs[t] = g_G[(size_t)2*GSTR + off];
    }
    if (tid < 9) sE[tid] = 0.f;
    __syncthreads();
    float e[9];
#pragma unroll
    for (int i = 0; i < 9; i++) e[i] = 0.f;
    for (int idx = tid; idx < 324; idx += 128){
        float q0 = Qs[idx], q1 = Qs[324+idx], q2 = Qs[648+idx];
        float k0 = Ks[idx], k1 = Ks[324+idx], k2 = Ks[648+idx];
        float d;
        d = q0-k0; e[0] += d*d;  d = q0-k1; e[1] += d*d;  d = q0-k2; e[2] += d*d;
        d = q1-k0; e[3] += d*d;  d = q1-k1; e[4] += d*d;  d = q1-k2; e[5] += d*d;
        d = q2-k0; e[6] += d*d;  d = q2-k1; e[7] += d*d;  d = q2-k2; e[8] += d*d;
    }
#pragma unroll
    for (int i = 0; i < 9; i++){
        float v = warp_sum(e[i]);
        if ((tid & 31) == 0) atomicAdd(&sE[i], v);
    }
    __syncthreads();
    if (tid == 0){
        for (int j = 0; j < 3; j++){
            float s0 = 1.f/(1.f + log1pf(sE[j*3+0]));
            float s1 = 1.f/(1.f + log1pf(sE[j*3+1]));
            float s2 = 1.f/(1.f + log1pf(sE[j*3+2]));
            float mx = fmaxf(s0, fmaxf(s1, s2));
            float e0 = expf(s0-mx), e1 = expf(s1-mx), e2 = expf(s2-mx);
            float inv = 1.f/(e0+e1+e2);
            sP[j*3+0] = e0*inv; sP[j*3+1] = e1*inv; sP[j*3+2] = e2*inv;
        }
    }
    __syncthreads();
    for (int idx = tid; idx < NM*324; idx += 128){
        int j = idx/324, ee = idx%324;
        float v = sP[j*3+0]*Vs[ee] + sP[j*3+1]*Vs[324+ee] + sP[j*3+2]*Vs[648+ee];
        g_mix[((size_t)b*NM + j)*324 + ee] = v;
    }
}

// ---------------- K8: triu-vec @ Wl + bl ----------------
__global__ void k_final(const float* __restrict__ Wl, const float* __restrict__ bl,
                        float* __restrict__ out){
    __shared__ float red[4];
    int tid = threadIdx.x, b = blockIdx.x;
    if (tid < 4) red[tid] = 0.f;
    __syncthreads();
    float a0 = 0.f, a1 = 0.f, a2 = 0.f, a3 = 0.f;
    for (int idx = tid; idx < 513; idx += 128){
        int m = idx/171, t = idx%171;
        int r = 0, rem = t;
        while (rem >= NE - r){ rem -= NE - r; r++; }
        int c = r + rem;
        float v = g_mix[((size_t)b*NM + m)*324 + r*NE + c];
        const float* wl = Wl + (size_t)idx*4;
        a0 += v*wl[0]; a1 += v*wl[1]; a2 += v*wl[2]; a3 += v*wl[3];
    }
    a0 = warp_sum(a0); a1 = warp_sum(a1); a2 = warp_sum(a2); a3 = warp_sum(a3);
    if ((tid & 31) == 0){
        atomicAdd(&red[0], a0); atomicAdd(&red[1], a1);
        atomicAdd(&red[2], a2); atomicAdd(&red[3], a3);
    }
    __syncthreads();
    if (tid < 4) out[b*4 + tid] = red[tid] + bl[tid];
}

// ---------------- host launcher ----------------
extern "C" void kernel_launch(void* const* d_in, const int* in_sizes, int n_in,
                              void* d_out, int out_size){
    const float* x   = (const float*)d_in[0];
    const float* W1  = (const float*)d_in[1];
    const float* b1  = (const float*)d_in[2];
    const float* g1  = (const float*)d_in[3];
    const float* be1 = (const float*)d_in[4];
    const float* W2  = (const float*)d_in[5];
    /* b2 = d_in[6] cancels */
    const float* g2  = (const float*)d_in[7];
    /* be2 = d_in[8] cancels */
    const float* Wq  = (const float*)d_in[9];
    const float* Wk  = (const float*)d_in[10];
    const float* Wv  = (const float*)d_in[11];
    const float* Wl  = (const float*)d_in[12];
    const float* bl  = (const float*)d_in[13];
    float* out = (float*)d_out;

    size_t conv_smem = (size_t)CONV_SMEM_FLOATS * sizeof(float);  // 97,792 B
    cudaFuncSetAttribute(k_conv, cudaFuncAttributeMaxDynamicSharedMemorySize, (int)conv_smem);

    k_init  <<<1, 256>>>();
    k_stats1<<<BS, 256>>>(x);
    k_prep  <<<1, 256>>>(W1, b1, g1, be1, W2);
    k_conv  <<<BS, CBLK, conv_smem>>>(x);
    k_bn2   <<<1, 32>>>(g2);
    k_qkv   <<<BS*NM, 128>>>(Wq, Wk, Wv);
    k_eig   <<<(3*BS*NM + EW-1)/EW, EW*32>>>(0, 3*BS*NM, 0);   // logQ/logK/logV
    k_attn  <<<BS, 128>>>();
    k_eig   <<<(BS*NM + EW-1)/EW, EW*32>>>(1, BS*NM, 1);       // logO (exp->rect->log collapsed)
    k_final <<<BS, 128>>>(Wl, bl, out);
}

// round 15
// speedup vs baseline: 1.6852x; 1.0027x over previous
#include <cuda_runtime.h>
#include <cuda_bf16.h>

#define BS 2048
#define HC 22
#define WX 438
#define C2 20
#define W2O 439
#define KW 12
#define NM 3
#define NE 18
#define NPAIR2 210      /* 20*21/2 */
#define NPAIR1 253      /* 22*23/2 */
#define GSTR (BS*NM*NE*NE)
#define LOGRECT (-9.210340371976184f)

// ---------------- device scratch (no cudaMalloc allowed) ----------------
__device__ float g_S[HC];
__device__ float g_Mu[NPAIR1];
__device__ float g_Wc[HC*KW*C2];     // [h][k][o]
__device__ float g_cpre[C2*13];      // prefix sums of cconst per o
__device__ float g_sum2[C2];
__device__ float g_sumsq2[C2];
__device__ float g_a2[C2];
__device__ float g_covy[(size_t)BS*NM*NPAIR2];   // packed centered grams
__device__ float g_G[(size_t)3*GSTR];            // Q,K,V then logQ,logK,logV in place
__device__ float g_mix[(size_t)BS*NM*NE*NE];     // mixed, then logO in place

__device__ __forceinline__ float warp_sum(float v){
#pragma unroll
    for (int o = 16; o; o >>= 1) v += __shfl_xor_sync(0xffffffffu, v, o);
    return v;
}

// ---------------- K0: zero accumulators ----------------
__global__ void k_init(){
    int t = threadIdx.x;
    if (t < HC)     g_S[t]  = 0.f;
    if (t < NPAIR1) g_Mu[t] = 0.f;
    if (t < C2){ g_sum2[t] = 0.f; g_sumsq2[t] = 0.f; }
}

// ---------------- K1: per-channel sum + Gram of x ----------------
__global__ void k_stats1(const float* __restrict__ x){
    __shared__ float xs[HC*439];   // pitch 439 (odd -> conflict free col access)
    int tid = threadIdx.x, b = blockIdx.x;
    const float* xb = x + (size_t)b*HC*WX;
    for (int idx = tid; idx < HC*WX; idx += 256)
        xs[(idx/WX)*439 + idx%WX] = xb[idx];
    __syncthreads();
    for (int task = tid; task < NPAIR1 + HC; task += 256){
        if (task < NPAIR1){
            int c = 0, rem = task;
            while (rem >= HC - c){ rem -= HC - c; c++; }
            int d = c + rem;
            const float* rc = xs + c*439;
            const float* rd = xs + d*439;
            float s = 0.f;
            for (int w = 0; w < WX; w++) s += rc[w]*rd[w];
            atomicAdd(&g_Mu[task], s);
        } else {
            int h = task - NPAIR1;
            const float* rh = xs + h*439;
            float s = 0.f;
            for (int w = 0; w < WX; w++) s += rh[w];
            atomicAdd(&g_S[h], s);
        }
    }
}

// ---------------- K2: fold conv1+BN1 into composite conv2 weights ----------------
__global__ void k_prep(const float* __restrict__ W1, const float* __restrict__ b1,
                       const float* __restrict__ g1, const float* __restrict__ be1,
                       const float* __restrict__ W2){
    __shared__ float mx[HC], Cx[HC*HC], W1s[HC*HC], a1[HC], hc[HC], ccs[KW*C2];
    int tid = threadIdx.x;
    const float invN = 1.f/((float)BS*(float)WX);
    if (tid < HC) mx[tid] = g_S[tid]*invN;
    for (int t = tid; t < HC*HC; t += blockDim.x) W1s[t] = W1[t];  // [o][h]
    __syncthreads();
    for (int t = tid; t < NPAIR1; t += blockDim.x){
        int c = 0, rem = t;
        while (rem >= HC - c){ rem -= HC - c; c++; }
        int d = c + rem;
        float v = g_Mu[t]*invN - mx[c]*mx[d];
        Cx[c*HC+d] = v; Cx[d*HC+c] = v;
    }
    __syncthreads();
    if (tid < HC){
        int o = tid;
        float m1 = b1[o];
        for (int h = 0; h < HC; h++) m1 += W1s[o*HC+h]*mx[h];
        float var = 0.f;
        for (int h = 0; h < HC; h++){
            float wh = W1s[o*HC+h];
            float s = 0.f;
            for (int h2 = 0; h2 < HC; h2++) s += W1s[o*HC+h2]*Cx[h*HC+h2];
            var += wh*s;
        }
        float a = g1[o]*rsqrtf(var + 1e-5f);
        a1[o] = a;
        hc[o] = a*(b1[o]-m1) + be1[o];     // constant part of h1
    }
    __syncthreads();
    for (int t = tid; t < KW*C2; t += blockDim.x){
        int k = t/C2, o = t%C2;
        float s = 0.f;
        for (int c = 0; c < HC; c++) s += W2[(o*HC+c)*KW+k]*hc[c];
        ccs[k*C2+o] = s;
    }
    for (int t = tid; t < HC*KW*C2; t += blockDim.x){
        int o = t%C2; int hk = t/C2; int k = hk%KW; int h = hk/KW;
        float s = 0.f;
        for (int c = 0; c < HC; c++) s += W2[(o*HC+c)*KW+k]*a1[c]*W1s[c*HC+h];
        g_Wc[t] = s;
    }
    __syncthreads();
    if (tid < C2){
        int o = tid; float run = 0.f;
        g_cpre[o*13+0] = 0.f;
        for (int k = 0; k < KW; k++){ run += ccs[k*C2+o]; g_cpre[o*13+k+1] = run; }
    }
}

// ---------------- K3: conv2 (on x) + patch covariances + BN2 sums ----------------
#define PX 454
#define PY 443
#define CHW 13
#define NCHK 34
#define CBLK 340
#define CONV_SMEM_FLOATS (HC*PX + C2*PY + HC*KW*C2 + C2*13 + NM*C2)

__global__ void __launch_bounds__(CBLK) k_conv(const float* __restrict__ x){
    extern __shared__ float sm[];
    float* xs  = sm;                   // HC*PX, zero-padded 6 both sides
    float* ys  = xs + HC*PX;           // C2*PY
    float* wcs = ys + C2*PY;           // HC*KW*C2
    float* cps = wcs + HC*KW*C2;       // C2*13
    float* Sp  = cps + C2*13;          // NM*C2
    int tid = threadIdx.x, b = blockIdx.x;
    const float* xb = x + (size_t)b*HC*WX;
    for (int idx = tid; idx < HC*PX; idx += CBLK){
        int h = idx/PX, c = idx%PX;
        xs[idx] = (c >= 6 && c < 6+WX) ? xb[h*WX + (c-6)] : 0.f;
    }
    for (int idx = tid; idx < HC*KW*C2; idx += CBLK) wcs[idx] = g_Wc[idx];
    for (int idx = tid; idx < C2*13; idx += CBLK)    cps[idx] = g_cpre[idx];
    __syncthreads();

    for (int task = tid; task < C2*NCHK; task += CBLK){
        int o = task / NCHK, ch = task % NCHK;
        int wbase = ch*CHW;
        float acc[CHW];
#pragma unroll
        for (int j = 0; j < CHW; j++) acc[j] = 0.f;
        for (int h = 0; h < HC; h++){
            const float* xr0 = xs + h*PX + wbase;
            float xr[CHW+KW-1];
#pragma unroll
            for (int c = 0; c < CHW+KW-1; c++) xr[c] = xr0[c];
            const float* wrow = wcs + h*KW*C2 + o;
#pragma unroll
            for (int k = 0; k < KW; k++){
                float wv = wrow[k*C2];
#pragma unroll
                for (int j = 0; j < CHW; j++) acc[j] += wv*xr[j+k];
            }
        }
#pragma unroll
        for (int j = 0; j < CHW; j++){
            int w = wbase + j;
            if (w < W2O){
                int kmin = 6 - w;   if (kmin < 0)  kmin = 0;
                int kmax = 444 - w; if (kmax > KW) kmax = KW;
                acc[j] += cps[o*13+kmax] - cps[o*13+kmin];
                ys[o*PY + w] = acc[j];
            }
        }
    }
    __syncthreads();

    // per-patch channel sums
    if (tid < NM*C2){
        int m = tid/C2, c = tid%C2;
        int lo = (m==0)?0:(m==1?147:293);
        int hi = (m==0)?147:(m==1?293:439);
        float s = 0.f;
        const float* yc = ys + c*PY;
        for (int w = lo; w < hi; w++) s += yc[w];
        Sp[m*C2+c] = s;
    }
    __syncthreads();

    // per-patch centered grams + BN2 sums
    if (tid < NPAIR2){
        int c = 0, rem = tid;
        while (rem >= C2 - c){ rem -= C2 - c; c++; }
        int d = c + rem;
        const float* yc = ys + c*PY;
        const float* yd = ys + d*PY;
        float sq = 0.f;
        for (int m = 0; m < NM; m++){
            int lo = (m==0)?0:(m==1?147:293);
            int hi = (m==0)?147:(m==1?293:439);
            float pp = 0.f;
            for (int w = lo; w < hi; w++) pp += yc[w]*yd[w];
            float L = (float)(hi - lo);
            float cc = pp - Sp[m*C2+c]*Sp[m*C2+d]/L;
            g_covy[((size_t)(b*NM+m))*NPAIR2 + tid] = cc;
            if (c == d) sq += pp;
        }
        if (c == d){
            atomicAdd(&g_sumsq2[c], sq);
            atomicAdd(&g_sum2[c], Sp[0*C2+c] + Sp[1*C2+c] + Sp[2*C2+c]);
        }
    }
}

// ---------------- K4: BN2 scale ----------------
__global__ void k_bn2(const float* __restrict__ g2){
    int o = threadIdx.x;
    if (o < C2){
        const float invN = 1.f/((float)BS*(float)W2O);
        float mean = g_sum2[o]*invN;
        float var  = g_sumsq2[o]*invN - mean*mean;
        g_a2[o] = g2[o]*rsqrtf(var + 1e-5f);
    }
}

// ---------------- K5: build Q,K,V = W^T X W ----------------
__global__ void k_qkv(const float* __restrict__ Wq, const float* __restrict__ Wk,
                      const float* __restrict__ Wv){
    __shared__ float a2s[C2], Xs[C2*21], Ws[3*C2*NE], Ts[C2*NE];
    __shared__ float invt;
    int tid = threadIdx.x; int bm = blockIdx.x;
    if (tid < C2) a2s[tid] = g_a2[tid];
    for (int t = tid; t < C2*NE; t += 128){
        Ws[t] = Wq[t]; Ws[C2*NE+t] = Wk[t]; Ws[2*C2*NE+t] = Wv[t];
    }
    __syncthreads();
    for (int t = tid; t < NPAIR2; t += 128){
        int c = 0, rem = t;
        while (rem >= C2 - c){ rem -= C2 - c; c++; }
        int d = c + rem;
        float v = a2s[c]*a2s[d]*g_covy[(size_t)bm*NPAIR2 + t];
        Xs[c*21+d] = v; Xs[d*21+c] = v;
    }
    __syncthreads();
    if (tid == 0){
        float tr = 0.f;
        for (int c = 0; c < C2; c++) tr += Xs[c*21+c];
        invt = 1.f/tr;
    }
    __syncthreads();
    for (int pl = 0; pl < 3; pl++){
        const float* W = Ws + pl*C2*NE;
        for (int t = tid; t < C2*NE; t += 128){
            int i = t/NE, j = t%NE;
            float s = 0.f;
            for (int p = 0; p < C2; p++) s += Xs[i*21+p]*W[p*NE+j];
            Ts[t] = s*invt + 1e-5f*W[i*NE+j];      // (X/tr + 1e-5 I) W
        }
        __syncthreads();
        float* dst = g_G + (size_t)pl*GSTR + (size_t)bm*NE*NE;
        for (int t = tid; t < NE*NE; t += 128){
            int i = t/NE, j = t%NE;
            float s = 0.f;
            for (int p = 0; p < C2; p++) s += W[p*NE+i]*Ts[p*NE+j];
            dst[t] = s;
        }
        __syncthreads();
    }
}

// ---------------- K6: tournament Jacobi eigh — instruction-diet version ----------------
// Changes vs R14: (a) incremental (k,j)/(k,i,ib) item indexing (no per-item division,
// lane-constant init), (b) dual param tables: sR holds premultiplied row offsets,
// sC holds raw column offsets (no per-item IMADs), (c) off-norm scan skipped for
// sweeps 0-2 (never converge that early; identity rotations keep correctness).
#define EPIT 19
#define EW 8
__global__ void __launch_bounds__(EW*32) k_eig(int which, int nmat, int mode){
    __shared__ float  sA[EW][NE*EPIT];
    __shared__ float  sV[EW][NE*EPIT];
    __shared__ float4 sR[EW][9];   // (c, s, p*EPIT, q*EPIT) as float-bits
    __shared__ float4 sC[EW][9];   // (c, s, p, q) as float-bits
    int lane = threadIdx.x & 31, wid = threadIdx.x >> 5;
    int mat = blockIdx.x*EW + wid;
    if (mat >= nmat) return;
    float* A = sA[wid];
    float* V = sV[wid];
    float* src = (which ? g_mix : g_G) + (size_t)mat*NE*NE;

    // lane-constant item-schedule seeds (3 registers)
    const int k0  = lane >= 18 ? 1 : 0;
    const int j0  = lane - 18*k0;
    const int ib0 = j0*EPIT;

    float na = 0.f;
    for (int idx = lane; idx < NE*NE; idx += 32){
        int i = idx/NE, j = idx - i*NE;
        float v = 0.5f*(src[idx] + src[j*NE+i]);  // symmetrize
        A[i*EPIT+j] = v;
        V[i*EPIT+j] = (i == j) ? 1.f : 0.f;
        na += v*v;
    }
    na = warp_sum(na);
    float thr = 1e-13f*na + 1e-37f;
    __syncwarp();

    for (int sweep = 0; sweep < 16; sweep++){
        if (sweep >= 3){
            float off = 0.f;
            for (int idx = lane; idx < NE*NE; idx += 32){
                int i = idx/NE, j = idx - i*NE;
                if (i != j){ float v = A[i*EPIT+j]; off += v*v; }
            }
            off = warp_sum(off);
            if (off <= thr) break;
        }

        for (int r = 0; r < 17; r++){
            if (lane < 9){
                int a, b;
                if (lane == 0){ a = 0; b = 1 + (16 + r) % 17; }
                else { a = 1 + (lane - 1 + r) % 17; b = 1 + (16 - lane + r) % 17; }
                int p = min(a, b), q = max(a, b);
                float apq = A[p*EPIT+q];
                float c = 1.f, s = 0.f;
                if (apq != 0.f){
                    float app = A[p*EPIT+p], aqq = A[q*EPIT+q];
                    float tau = (aqq - app)/(2.f*apq);
                    float t = ((tau >= 0.f) ? 1.f : -1.f)/(fabsf(tau) + sqrtf(1.f + tau*tau));
                    c = rsqrtf(1.f + t*t);
                    s = t*c;
                }
                sR[wid][lane] = make_float4(c, s, __int_as_float(p*EPIT), __int_as_float(q*EPIT));
                sC[wid][lane] = make_float4(c, s, __int_as_float(p), __int_as_float(q));
            }
            __syncwarp();
            // row updates: items (k,j), k=pair, j=column; incremental indexing
            {
                int k = k0, j = j0;
#pragma unroll
                for (int u = 0; u < 6; u++){
                    if (k < 9){
                        float4 pk = sR[wid][k];
                        int rp = __float_as_int(pk.z), rq = __float_as_int(pk.w);
                        float a0 = A[rp+j], a1 = A[rq+j];
                        A[rp+j] = pk.x*a0 - pk.y*a1;
                        A[rq+j] = pk.y*a0 + pk.x*a1;
                    }
                    k += 1; j += 14; if (j >= 18){ j -= 18; k += 1; }
                }
            }
            __syncwarp();
            // column + eigenvector updates: items (k,i); ib = i*EPIT tracked incrementally
            {
                int k = k0, i = j0, ib = ib0;
#pragma unroll
                for (int u = 0; u < 6; u++){
                    if (k < 9){
                        float4 pk = sC[wid][k];
                        int p = __float_as_int(pk.z), q = __float_as_int(pk.w);
                        float aip = A[ib+p], aiq = A[ib+q];
                        A[ib+p] = pk.x*aip - pk.y*aiq;
                        A[ib+q] = pk.y*aip + pk.x*aiq;
                        float vip = V[ib+p], viq = V[ib+q];
                        V[ib+p] = pk.x*vip - pk.y*viq;
                        V[ib+q] = pk.y*vip + pk.x*viq;
                    }
                    k += 1; i += 14; ib += 14*EPIT;
                    if (i >= 18){ i -= 18; ib -= 18*EPIT; k += 1; }
                }
            }
            __syncwarp();
        }
    }
    __syncwarp();
    if (lane < NE){
        float wj[NE];
#pragma unroll
        for (int k = 0; k < NE; k++){
            float lam = A[k*EPIT+k];
            float f = mode ? fmaxf(lam, LOGRECT) : logf(fmaxf(lam, 1e-30f));
            wj[k] = f * V[lane*EPIT+k];
        }
        for (int i = 0; i < NE; i++){
            float s = 0.f;
#pragma unroll
            for (int k = 0; k < NE; k++) s += V[i*EPIT+k]*wj[k];
            src[i*NE+lane] = s;
        }
    }
}

// ---------------- K7: energy / softmax / mix ----------------
__global__ void k_attn(){
    __shared__ float Qs[NM*324], Ks[NM*324], Vs[NM*324], sE[9], sP[9];
    int tid = threadIdx.x, b = blockIdx.x;
    for (int t = tid; t < NM*324; t += 128){
        size_t off = (size_t)b*NM*324 + t;
        Qs[t] = g_G[off];
        Ks[t] = g_G[(size_t)GSTR + off];
        Vs[t] = g_G[(size_t)2*GSTR + off];
    }
    if (tid < 9) sE[tid] = 0.f;
    __syncthreads();
    float e[9];
#pragma unroll
    for (int i = 0; i < 9; i++) e[i] = 0.f;
    for (int idx = tid; idx < 324; idx += 128){
        float q0 = Qs[idx], q1 = Qs[324+idx], q2 = Qs[648+idx];
        float k0 = Ks[idx], k1 = Ks[324+idx], k2 = Ks[648+idx];
        float d;
        d = q0-k0; e[0] += d*d;  d = q0-k1; e[1] += d*d;  d = q0-k2; e[2] += d*d;
        d = q1-k0; e[3] += d*d;  d = q1-k1; e[4] += d*d;  d = q1-k2; e[5] += d*d;
        d = q2-k0; e[6] += d*d;  d = q2-k1; e[7] += d*d;  d = q2-k2; e[8] += d*d;
    }
#pragma unroll
    for (int i = 0; i < 9; i++){
        float v = warp_sum(e[i]);
        if ((tid & 31) == 0) atomicAdd(&sE[i], v);
    }
    __syncthreads();
    if (tid == 0){
        for (int j = 0; j < 3; j++){
            float s0 = 1.f/(1.f + log1pf(sE[j*3+0]));
            float s1 = 1.f/(1.f + log1pf(sE[j*3+1]));
            float s2 = 1.f/(1.f + log1pf(sE[j*3+2]));
            float mx = fmaxf(s0, fmaxf(s1, s2));
            float e0 = expf(s0-mx), e1 = expf(s1-mx), e2 = expf(s2-mx);
            float inv = 1.f/(e0+e1+e2);
            sP[j*3+0] = e0*inv; sP[j*3+1] = e1*inv; sP[j*3+2] = e2*inv;
        }
    }
    __syncthreads();
    for (int idx = tid; idx < NM*324; idx += 128){
        int j = idx/324, ee = idx%324;
        float v = sP[j*3+0]*Vs[ee] + sP[j*3+1]*Vs[324+ee] + sP[j*3+2]*Vs[648+ee];
        g_mix[((size_t)b*NM + j)*324 + ee] = v;
    }
}

// ---------------- K8: triu-vec @ Wl + bl ----------------
__global__ void k_final(const float* __restrict__ Wl, const float* __restrict__ bl,
                        float* __restrict__ out){
    __shared__ float red[4];
    int tid = threadIdx.x, b = blockIdx.x;
    if (tid < 4) red[tid] = 0.f;
    __syncthreads();
    float a0 = 0.f, a1 = 0.f, a2 = 0.f, a3 = 0.f;
    for (int idx = tid; idx < 513; idx += 128){
        int m = idx/171, t = idx%171;
        int r = 0, rem = t;
        while (rem >= NE - r){ rem -= NE - r; r++; }
        int c = r + rem;
        float v = g_mix[((size_t)b*NM + m)*324 + r*NE + c];
        const float* wl = Wl + (size_t)idx*4;
        a0 += v*wl[0]; a1 += v*wl[1]; a2 += v*wl[2]; a3 += v*wl[3];
    }
    a0 = warp_sum(a0); a1 = warp_sum(a1); a2 = warp_sum(a2); a3 = warp_sum(a3);
    if ((tid & 31) == 0){
        atomicAdd(&red[0], a0); atomicAdd(&red[1], a1);
        atomicAdd(&red[2], a2); atomicAdd(&red[3], a3);
    }
    __syncthreads();
    if (tid < 4) out[b*4 + tid] = red[tid] + bl[tid];
}

// ---------------- host launcher ----------------
extern "C" void kernel_launch(void* const* d_in, const int* in_sizes, int n_in,
                              void* d_out, int out_size){
    const float* x   = (const float*)d_in[0];
    const float* W1  = (const float*)d_in[1];
    const float* b1  = (const float*)d_in[2];
    const float* g1  = (const float*)d_in[3];
    const float* be1 = (const float*)d_in[4];
    const float* W2  = (const float*)d_in[5];
    /* b2 = d_in[6] cancels */
    const float* g2  = (const float*)d_in[7];
    /* be2 = d_in[8] cancels */
    const float* Wq  = (const float*)d_in[9];
    const float* Wk  = (const float*)d_in[10];
    const float* Wv  = (const float*)d_in[11];
    const float* Wl  = (const float*)d_in[12];
    const float* bl  = (const float*)d_in[13];
    float* out = (float*)d_out;

    size_t conv_smem = (size_t)CONV_SMEM_FLOATS * sizeof(float);  // 97,792 B
    cudaFuncSetAttribute(k_conv, cudaFuncAttributeMaxDynamicSharedMemorySize, (int)conv_smem);

    k_init  <<<1, 256>>>();
    k_stats1<<<BS, 256>>>(x);
    k_prep  <<<1, 256>>>(W1, b1, g1, be1, W2);
    k_conv  <<<BS, CBLK, conv_smem>>>(x);
    k_bn2   <<<1, 32>>>(g2);
    k_qkv   <<<BS*NM, 128>>>(Wq, Wk, Wv);
    k_eig   <<<(3*BS*NM + EW-1)/EW, EW*32>>>(0, 3*BS*NM, 0);   // logQ/logK/logV
    k_attn  <<<BS, 128>>>();
    k_eig   <<<(BS*NM + EW-1)/EW, EW*32>>>(1, BS*NM, 1);       // logO (exp->rect->log collapsed)
    k_final <<<BS, 128>>>(Wl, bl, out);
}

// round 17
// speedup vs baseline: 1.7444x; 1.0351x over previous
#include <cuda_runtime.h>
#include <cuda_bf16.h>

#define BS 2048
#define HC 22
#define WX 438
#define C2 20
#define W2O 439
#define KW 12
#define NM 3
#define NE 18
#define NPAIR2 210      /* 20*21/2 */
#define NPAIR1 253      /* 22*23/2 */
#define GSTR (BS*NM*NE*NE)
#define LOGRECT (-9.210340371976184f)

// ---------------- device scratch (no cudaMalloc allowed) ----------------
__device__ float g_S[HC];
__device__ float g_Mu[NPAIR1];
__device__ float g_Wc[HC*KW*C2];     // [h][k][o]
__device__ float g_cpre[C2*13];      // prefix sums of cconst per o
__device__ float g_sum2[C2];
__device__ float g_sumsq2[C2];
__device__ float g_a2[C2];
__device__ float g_covy[(size_t)BS*NM*NPAIR2];   // packed centered grams
__device__ float g_G[(size_t)3*GSTR];            // Q,K,V then logQ,logK,logV in place
__device__ float g_mix[(size_t)BS*NM*NE*NE];     // mixed, then logO in place

__device__ __forceinline__ float warp_sum(float v){
#pragma unroll
    for (int o = 16; o; o >>= 1) v += __shfl_xor_sync(0xffffffffu, v, o);
    return v;
}

// ---------------- K0: zero accumulators ----------------
__global__ void k_init(){
    int t = threadIdx.x;
    if (t < HC)     g_S[t]  = 0.f;
    if (t < NPAIR1) g_Mu[t] = 0.f;
    if (t < C2){ g_sum2[t] = 0.f; g_sumsq2[t] = 0.f; }
}

// ---------------- K1: per-channel sum + Gram of x ----------------
__global__ void k_stats1(const float* __restrict__ x){
    __shared__ float xs[HC*439];   // pitch 439 (odd -> conflict free col access)
    int tid = threadIdx.x, b = blockIdx.x;
    const float* xb = x + (size_t)b*HC*WX;
    for (int idx = tid; idx < HC*WX; idx += 256)
        xs[(idx/WX)*439 + idx%WX] = xb[idx];
    __syncthreads();
    for (int task = tid; task < NPAIR1 + HC; task += 256){
        if (task < NPAIR1){
            int c = 0, rem = task;
            while (rem >= HC - c){ rem -= HC - c; c++; }
            int d = c + rem;
            const float* rc = xs + c*439;
            const float* rd = xs + d*439;
            float s = 0.f;
            for (int w = 0; w < WX; w++) s += rc[w]*rd[w];
            atomicAdd(&g_Mu[task], s);
        } else {
            int h = task - NPAIR1;
            const float* rh = xs + h*439;
            float s = 0.f;
            for (int w = 0; w < WX; w++) s += rh[w];
            atomicAdd(&g_S[h], s);
        }
    }
}

// ---------------- K2: fold conv1+BN1 into composite conv2 weights ----------------
__global__ void k_prep(const float* __restrict__ W1, const float* __restrict__ b1,
                       const float* __restrict__ g1, const float* __restrict__ be1,
                       const float* __restrict__ W2){
    __shared__ float mx[HC], Cx[HC*HC], W1s[HC*HC], a1[HC], hc[HC], ccs[KW*C2];
    int tid = threadIdx.x;
    const float invN = 1.f/((float)BS*(float)WX);
    if (tid < HC) mx[tid] = g_S[tid]*invN;
    for (int t = tid; t < HC*HC; t += blockDim.x) W1s[t] = W1[t];  // [o][h]
    __syncthreads();
    for (int t = tid; t < NPAIR1; t += blockDim.x){
        int c = 0, rem = t;
        while (rem >= HC - c){ rem -= HC - c; c++; }
        int d = c + rem;
        float v = g_Mu[t]*invN - mx[c]*mx[d];
        Cx[c*HC+d] = v; Cx[d*HC+c] = v;
    }
    __syncthreads();
    if (tid < HC){
        int o = tid;
        float m1 = b1[o];
        for (int h = 0; h < HC; h++) m1 += W1s[o*HC+h]*mx[h];
        float var = 0.f;
        for (int h = 0; h < HC; h++){
            float wh = W1s[o*HC+h];
            float s = 0.f;
            for (int h2 = 0; h2 < HC; h2++) s += W1s[o*HC+h2]*Cx[h*HC+h2];
            var += wh*s;
        }
        float a = g1[o]*rsqrtf(var + 1e-5f);
        a1[o] = a;
        hc[o] = a*(b1[o]-m1) + be1[o];     // constant part of h1
    }
    __syncthreads();
    for (int t = tid; t < KW*C2; t += blockDim.x){
        int k = t/C2, o = t%C2;
        float s = 0.f;
        for (int c = 0; c < HC; c++) s += W2[(o*HC+c)*KW+k]*hc[c];
        ccs[k*C2+o] = s;
    }
    for (int t = tid; t < HC*KW*C2; t += blockDim.x){
        int o = t%C2; int hk = t/C2; int k = hk%KW; int h = hk/KW;
        float s = 0.f;
        for (int c = 0; c < HC; c++) s += W2[(o*HC+c)*KW+k]*a1[c]*W1s[c*HC+h];
        g_Wc[t] = s;
    }
    __syncthreads();
    if (tid < C2){
        int o = tid; float run = 0.f;
        g_cpre[o*13+0] = 0.f;
        for (int k = 0; k < KW; k++){ run += ccs[k*C2+o]; g_cpre[o*13+k+1] = run; }
    }
}

// ---------------- K3: conv2 (on x) + patch covariances + BN2 sums ----------------
#define PX 454
#define PY 443
#define CHW 13
#define NCHK 34
#define CBLK 340
#define CONV_SMEM_FLOATS (HC*PX + C2*PY + HC*KW*C2 + C2*13 + NM*C2)

__global__ void __launch_bounds__(CBLK) k_conv(const float* __restrict__ x){
    extern __shared__ float sm[];
    float* xs  = sm;                   // HC*PX, zero-padded 6 both sides
    float* ys  = xs + HC*PX;           // C2*PY
    float* wcs = ys + C2*PY;           // HC*KW*C2
    float* cps = wcs + HC*KW*C2;       // C2*13
    float* Sp  = cps + C2*13;          // NM*C2
    int tid = threadIdx.x, b = blockIdx.x;
    const float* xb = x + (size_t)b*HC*WX;
    for (int idx = tid; idx < HC*PX; idx += CBLK){
        int h = idx/PX, c = idx%PX;
        xs[idx] = (c >= 6 && c < 6+WX) ? xb[h*WX + (c-6)] : 0.f;
    }
    for (int idx = tid; idx < HC*KW*C2; idx += CBLK) wcs[idx] = g_Wc[idx];
    for (int idx = tid; idx < C2*13; idx += CBLK)    cps[idx] = g_cpre[idx];
    __syncthreads();

    for (int task = tid; task < C2*NCHK; task += CBLK){
        int o = task / NCHK, ch = task % NCHK;
        int wbase = ch*CHW;
        float acc[CHW];
#pragma unroll
        for (int j = 0; j < CHW; j++) acc[j] = 0.f;
        for (int h = 0; h < HC; h++){
            const float* xr0 = xs + h*PX + wbase;
            float xr[CHW+KW-1];
#pragma unroll
            for (int c = 0; c < CHW+KW-1; c++) xr[c] = xr0[c];
            const float* wrow = wcs + h*KW*C2 + o;
#pragma unroll
            for (int k = 0; k < KW; k++){
                float wv = wrow[k*C2];
#pragma unroll
                for (int j = 0; j < CHW; j++) acc[j] += wv*xr[j+k];
            }
        }
#pragma unroll
        for (int j = 0; j < CHW; j++){
            int w = wbase + j;
            if (w < W2O){
                int kmin = 6 - w;   if (kmin < 0)  kmin = 0;
                int kmax = 444 - w; if (kmax > KW) kmax = KW;
                acc[j] += cps[o*13+kmax] - cps[o*13+kmin];
                ys[o*PY + w] = acc[j];
            }
        }
    }
    __syncthreads();

    // per-patch channel sums
    if (tid < NM*C2){
        int m = tid/C2, c = tid%C2;
        int lo = (m==0)?0:(m==1?147:293);
        int hi = (m==0)?147:(m==1?293:439);
        float s = 0.f;
        const float* yc = ys + c*PY;
        for (int w = lo; w < hi; w++) s += yc[w];
        Sp[m*C2+c] = s;
    }
    __syncthreads();

    // per-patch centered grams + BN2 sums
    if (tid < NPAIR2){
        int c = 0, rem = tid;
        while (rem >= C2 - c){ rem -= C2 - c; c++; }
        int d = c + rem;
        const float* yc = ys + c*PY;
        const float* yd = ys + d*PY;
        float sq = 0.f;
        for (int m = 0; m < NM; m++){
            int lo = (m==0)?0:(m==1?147:293);
            int hi = (m==0)?147:(m==1?293:439);
            float pp = 0.f;
            for (int w = lo; w < hi; w++) pp += yc[w]*yd[w];
            float L = (float)(hi - lo);
            float cc = pp - Sp[m*C2+c]*Sp[m*C2+d]/L;
            g_covy[((size_t)(b*NM+m))*NPAIR2 + tid] = cc;
            if (c == d) sq += pp;
        }
        if (c == d){
            atomicAdd(&g_sumsq2[c], sq);
            atomicAdd(&g_sum2[c], Sp[0*C2+c] + Sp[1*C2+c] + Sp[2*C2+c]);
        }
    }
}

// ---------------- K4: BN2 scale ----------------
__global__ void k_bn2(const float* __restrict__ g2){
    int o = threadIdx.x;
    if (o < C2){
        const float invN = 1.f/((float)BS*(float)W2O);
        float mean = g_sum2[o]*invN;
        float var  = g_sumsq2[o]*invN - mean*mean;
        g_a2[o] = g2[o]*rsqrtf(var + 1e-5f);
    }
}

// ---------------- K5: build Q,K,V = W^T X W ----------------
__global__ void k_qkv(const float* __restrict__ Wq, const float* __restrict__ Wk,
                      const float* __restrict__ Wv){
    __shared__ float a2s[C2], Xs[C2*21], Ws[3*C2*NE], Ts[C2*NE];
    __shared__ float invt;
    int tid = threadIdx.x; int bm = blockIdx.x;
    if (tid < C2) a2s[tid] = g_a2[tid];
    for (int t = tid; t < C2*NE; t += 128){
        Ws[t] = Wq[t]; Ws[C2*NE+t] = Wk[t]; Ws[2*C2*NE+t] = Wv[t];
    }
    __syncthreads();
    for (int t = tid; t < NPAIR2; t += 128){
        int c = 0, rem = t;
        while (rem >= C2 - c){ rem -= C2 - c; c++; }
        int d = c + rem;
        float v = a2s[c]*a2s[d]*g_covy[(size_t)bm*NPAIR2 + t];
        Xs[c*21+d] = v; Xs[d*21+c] = v;
    }
    __syncthreads();
    if (tid == 0){
        float tr = 0.f;
        for (int c = 0; c < C2; c++) tr += Xs[c*21+c];
        invt = 1.f/tr;
    }
    __syncthreads();
    for (int pl = 0; pl < 3; pl++){
        const float* W = Ws + pl*C2*NE;
        for (int t = tid; t < C2*NE; t += 128){
            int i = t/NE, j = t%NE;
            float s = 0.f;
            for (int p = 0; p < C2; p++) s += Xs[i*21+p]*W[p*NE+j];
            Ts[t] = s*invt + 1e-5f*W[i*NE+j];      // (X/tr + 1e-5 I) W
        }
        __syncthreads();
        float* dst = g_G + (size_t)pl*GSTR + (size_t)bm*NE*NE;
        for (int t = tid; t < NE*NE; t += 128){
            int i = t/NE, j = t%NE;
            float s = 0.f;
            for (int p = 0; p < C2; p++) s += W[p*NE+i]*Ts[p*NE+j];
            dst[t] = s;
        }
        __syncthreads();
    }
}

// ---------------- K6: tournament Jacobi eigh — SMEM-traffic-diet version ----------------
// k_eig is SMEM-crossbar (128B/cyc/SM) bound, NOT issue bound. This version cuts
// SMEM bytes: (a) threshold-skip: pairs with apq^2 <= thr/512 publish identity and
// their row/col items skip ALL LDS/STS (group-uniform branch; exact — identity
// rotation is a no-op; residual off-norm <= 153*thr/512 ~ 0.3*thr), (b) exit
// threshold loosened 1e-13 -> 1e-11 (off <= 3e-6*||A||_F at exit, well inside the
// 1e-3 gate), (c) convergence scan every sweep from sweep 2 (11 warp-LDS, cheap).
#define EPIT 19
#define EW 8
__global__ void __launch_bounds__(EW*32) k_eig(int which, int nmat, int mode){
    __shared__ float  sA[EW][NE*EPIT];
    __shared__ float  sV[EW][NE*EPIT];
    __shared__ float4 sR[EW][9];   // (c, s, p*EPIT, q*EPIT) as float-bits
    __shared__ float4 sC[EW][9];   // (c, s, p, q) as float-bits
    int lane = threadIdx.x & 31, wid = threadIdx.x >> 5;
    int mat = blockIdx.x*EW + wid;
    if (mat >= nmat) return;
    float* A = sA[wid];
    float* V = sV[wid];
    float* src = (which ? g_mix : g_G) + (size_t)mat*NE*NE;

    // lane-constant item-schedule seeds
    const int k0  = lane >= 18 ? 1 : 0;
    const int j0  = lane - 18*k0;
    const int ib0 = j0*EPIT;

    float na = 0.f;
    for (int idx = lane; idx < NE*NE; idx += 32){
        int i = idx/NE, j = idx - i*NE;
        float v = 0.5f*(src[idx] + src[j*NE+i]);  // symmetrize
        A[i*EPIT+j] = v;
        V[i*EPIT+j] = (i == j) ? 1.f : 0.f;
        na += v*v;
    }
    na = warp_sum(na);
    float thr  = 1e-11f*na + 1e-37f;
    float skipt = thr*(1.f/512.f);
    __syncwarp();

    for (int sweep = 0; sweep < 16; sweep++){
        if (sweep >= 2){
            float off = 0.f;
            for (int idx = lane; idx < NE*NE; idx += 32){
                int i = idx/NE, j = idx - i*NE;
                if (i != j){ float v = A[i*EPIT+j]; off += v*v; }
            }
            off = warp_sum(off);
            if (off <= thr) break;
        }

        for (int r = 0; r < 17; r++){
            if (lane < 9){
                int a, b;
                if (lane == 0){ a = 0; b = 1 + (16 + r) % 17; }
                else { a = 1 + (lane - 1 + r) % 17; b = 1 + (16 - lane + r) % 17; }
                int p = min(a, b), q = max(a, b);
                float apq = A[p*EPIT+q];
                float c = 1.f, s = 0.f;
                if (apq*apq > skipt){
                    float app = A[p*EPIT+p], aqq = A[q*EPIT+q];
                    float tau = (aqq - app)/(2.f*apq);
                    float t = ((tau >= 0.f) ? 1.f : -1.f)/(fabsf(tau) + sqrtf(1.f + tau*tau));
                    c = rsqrtf(1.f + t*t);
                    s = t*c;
                }
                sR[wid][lane] = make_float4(c, s, __int_as_float(p*EPIT), __int_as_float(q*EPIT));
                sC[wid][lane] = make_float4(c, s, __int_as_float(p), __int_as_float(q));
            }
            __syncwarp();
            // row updates; skipped pairs (s==0) do zero SMEM traffic
            {
                int k = k0, j = j0;
#pragma unroll
                for (int u = 0; u < 6; u++){
                    if (k < 9){
                        float4 pk = sR[wid][k];
                        if (pk.y != 0.f){
                            int rp = __float_as_int(pk.z), rq = __float_as_int(pk.w);
                            float a0 = A[rp+j], a1 = A[rq+j];
                            A[rp+j] = pk.x*a0 - pk.y*a1;
                            A[rq+j] = pk.y*a0 + pk.x*a1;
                        }
                    }
                    k += 1; j += 14; if (j >= 18){ j -= 18; k += 1; }
                }
            }
            __syncwarp();
            // column + eigenvector updates; skipped pairs do zero SMEM traffic
            {
                int k = k0, i = j0, ib = ib0;
#pragma unroll
                for (int u = 0; u < 6; u++){
                    if (k < 9){
                        float4 pk = sC[wid][k];
                        if (pk.y != 0.f){
                            int p = __float_as_int(pk.z), q = __float_as_int(pk.w);
                            float aip = A[ib+p], aiq = A[ib+q];
                            A[ib+p] = pk.x*aip - pk.y*aiq;
                            A[ib+q] = pk.y*aip + pk.x*aiq;
                            float vip = V[ib+p], viq = V[ib+q];
                            V[ib+p] = pk.x*vip - pk.y*viq;
                            V[ib+q] = pk.y*vip + pk.x*viq;
                        }
                    }
                    k += 1; i += 14; ib += 14*EPIT;
                    if (i >= 18){ i -= 18; ib -= 18*EPIT; k += 1; }
                }
            }
            __syncwarp();
        }
    }
    __syncwarp();
    if (lane < NE){
        float wj[NE];
#pragma unroll
        for (int k = 0; k < NE; k++){
            float lam = A[k*EPIT+k];
            float f = mode ? fmaxf(lam, LOGRECT) : logf(fmaxf(lam, 1e-30f));
            wj[k] = f * V[lane*EPIT+k];
        }
        for (int i = 0; i < NE; i++){
            float s = 0.f;
#pragma unroll
            for (int k = 0; k < NE; k++) s += V[i*EPIT+k]*wj[k];
            src[i*NE+lane] = s;
        }
    }
}

// ---------------- K7: energy / softmax / mix ----------------
__global__ void k_attn(){
    __shared__ float Qs[NM*324], Ks[NM*324], Vs[NM*324], sE[9], sP[9];
    int tid = threadIdx.x, b = blockIdx.x;
    for (int t = tid; t < NM*324; t += 128){
        size_t off = (size_t)b*NM*324 + t;
        Qs[t] = g_G[off];
        Ks[t] = g_G[(size_t)GSTR + off];
        Vs[t] = g_G[(size_t)2*GSTR + off];
    }
    if (tid < 9) sE[tid] = 0.f;
    __syncthreads();
    float e[9];
#pragma unroll
    for (int i = 0; i < 9; i++) e[i] = 0.f;
    for (int idx = tid; idx < 324; idx += 128){
        float q0 = Qs[idx], q1 = Qs[324+idx], q2 = Qs[648+idx];
        float k0 = Ks[idx], k1 = Ks[324+idx], k2 = Ks[648+idx];
        float d;
        d = q0-k0; e[0] += d*d;  d = q0-k1; e[1] += d*d;  d = q0-k2; e[2] += d*d;
        d = q1-k0; e[3] += d*d;  d = q1-k1; e[4] += d*d;  d = q1-k2; e[5] += d*d;
        d = q2-k0; e[6] += d*d;  d = q2-k1; e[7] += d*d;  d = q2-k2; e[8] += d*d;
    }
#pragma unroll
    for (int i = 0; i < 9; i++){
        float v = warp_sum(e[i]);
        if ((tid & 31) == 0) atomicAdd(&sE[i], v);
    }
    __syncthreads();
    if (tid == 0){
        for (int j = 0; j < 3; j++){
            float s0 = 1.f/(1.f + log1pf(sE[j*3+0]));
            float s1 = 1.f/(1.f + log1pf(sE[j*3+1]));
            float s2 = 1.f/(1.f + log1pf(sE[j*3+2]));
            float mx = fmaxf(s0, fmaxf(s1, s2));
            float e0 = expf(s0-mx), e1 = expf(s1-mx), e2 = expf(s2-mx);
            float inv = 1.f/(e0+e1+e2);
            sP[j*3+0] = e0*inv; sP[j*3+1] = e1*inv; sP[j*3+2] = e2*inv;
        }
    }
    __syncthreads();
    for (int idx = tid; idx < NM*324; idx += 128){
        int j = idx/324, ee = idx%324;
        float v = sP[j*3+0]*Vs[ee] + sP[j*3+1]*Vs[324+ee] + sP[j*3+2]*Vs[648+ee];
        g_mix[((size_t)b*NM + j)*324 + ee] = v;
    }
}

// ---------------- K8: triu-vec @ Wl + bl ----------------
__global__ void k_final(const float* __restrict__ Wl, const float* __restrict__ bl,
                        float* __restrict__ out){
    __shared__ float red[4];
    int tid = threadIdx.x, b = blockIdx.x;
    if (tid < 4) red[tid] = 0.f;
    __syncthreads();
    float a0 = 0.f, a1 = 0.f, a2 = 0.f, a3 = 0.f;
    for (int idx = tid; idx < 513; idx += 128){
        int m = idx/171, t = idx%171;
        int r = 0, rem = t;
        while (rem >= NE - r){ rem -= NE - r; r++; }
        int c = r + rem;
        float v = g_mix[((size_t)b*NM + m)*324 + r*NE + c];
        const float* wl = Wl + (size_t)idx*4;
        a0 += v*wl[0]; a1 += v*wl[1]; a2 += v*wl[2]; a3 += v*wl[3];
    }
    a0 = warp_sum(a0); a1 = warp_sum(a1); a2 = warp_sum(a2); a3 = warp_sum(a3);
    if ((tid & 31) == 0){
        atomicAdd(&red[0], a0); atomicAdd(&red[1], a1);
        atomicAdd(&red[2], a2); atomicAdd(&red[3], a3);
    }
    __syncthreads();
    if (tid < 4) out[b*4 + tid] = red[tid] + bl[tid];
}

// ---------------- host launcher ----------------
extern "C" void kernel_launch(void* const* d_in, const int* in_sizes, int n_in,
                              void* d_out, int out_size){
    const float* x   = (const float*)d_in[0];
    const float* W1  = (const float*)d_in[1];
    const float* b1  = (const float*)d_in[2];
    const float* g1  = (const float*)d_in[3];
    const float* be1 = (const float*)d_in[4];
    const float* W2  = (const float*)d_in[5];
    /* b2 = d_in[6] cancels */
    const float* g2  = (const float*)d_in[7];
    /* be2 = d_in[8] cancels */
    const float* Wq  = (const float*)d_in[9];
    const float* Wk  = (const float*)d_in[10];
    const float* Wv  = (const float*)d_in[11];
    const float* Wl  = (const float*)d_in[12];
    const float* bl  = (const float*)d_in[13];
    float* out = (float*)d_out;

    size_t conv_smem = (size_t)CONV_SMEM_FLOATS * sizeof(float);  // 97,792 B
    cudaFuncSetAttribute(k_conv, cudaFuncAttributeMaxDynamicSharedMemorySize, (int)conv_smem);

    k_init  <<<1, 256>>>();
    k_stats1<<<BS, 256>>>(x);
    k_prep  <<<1, 256>>>(W1, b1, g1, be1, W2);
    k_conv  <<<BS, CBLK, conv_smem>>>(x);
    k_bn2   <<<1, 32>>>(g2);
    k_qkv   <<<BS*NM, 128>>>(Wq, Wk, Wv);
    k_eig   <<<(3*BS*NM + EW-1)/EW, EW*32>>>(0, 3*BS*NM, 0);   // logQ/logK/logV
    k_attn  <<<BS, 128>>>();
    k_eig   <<<(BS*NM + EW-1)/EW, EW*32>>>(1, BS*NM, 1);       // logO (exp->rect->log collapsed)
    k_final <<<BS, 128>>>(Wl, bl, out);
}